// round 8
// baseline (speedup 1.0000x reference)
#include <cuda_runtime.h>
#include <cstdint>

// Problem constants: SUPPORT=(16,16), N_NODES=100000, F=64, B=4096
#define BATCH_N    4096
#define SUP        16
#define FDIM       64
#define ROW_LEN    65          // 1 weight col + 64 features
#define ROWS_PER_B 1088        // 2 * 16 * 34
#define GROUP_ROWS 34          // 2 + 2*16
#define N_GROUPS   (BATCH_N * 2 * SUP)        // 131072 groups
#define GROUPS_PER_BLOCK 4
#define THREADS    128                         // 4 warps, 1 group each
#define N_BLOCKS   (N_GROUPS / GROUPS_PER_BLOCK)       // 32768
#define CHUNK_FLOATS (GROUPS_PER_BLOCK * GROUP_ROWS * ROW_LEN)  // 8840 fl = 35360 B (16B-mult)
#define WCHUNK       (GROUPS_PER_BLOCK * GROUP_ROWS)            // 136 fl = 544 B (16B-mult)

__device__ __forceinline__ uint32_t smem_u32(const void* p) {
    uint32_t a;
    asm("{ .reg .u64 t; cvta.to.shared.u64 t, %1; cvt.u32.u64 %0, t; }" : "=r"(a) : "l"(p));
    return a;
}

__global__ __launch_bounds__(THREADS)
void gae_gather_tma_kernel(const int*   __restrict__ node_ids,
                           const float* __restrict__ features,
                           const int*   __restrict__ in_sample,
                           const int*   __restrict__ out_sample,
                           const float* __restrict__ in_amnt,
                           const float* __restrict__ out_amnt,
                           float*       __restrict__ feat_out,
                           float*       __restrict__ w_out) {
    __shared__ alignas(128) float buf [CHUNK_FLOATS];  // staged feat rows (output layout)
    __shared__ alignas(16)  float wbuf[WCHUNK];        // staged weights

    const int lane = threadIdx.x & 31;
    const int warp = threadIdx.x >> 5;                 // 0..3, owns group g0+warp
    const int g    = blockIdx.x * GROUPS_PER_BLOCK + warp;

    const int b    = g >> 5;        // 32 groups per batch element
    const int rem  = g & 31;
    const int half = rem >> 4;      // 0 = in-branch at hop1, 1 = out-branch
    const int i    = rem & 15;      // first-hop neighbor index

    const int n = node_ids[b];
    const int*   s1 = half ? out_sample : in_sample;
    const float* a1 = half ? out_amnt  : in_amnt;
    const int   n1 = s1[n * SUP + i];
    const float w1 = a1[n * SUP + i];

    // Per-lane precompute of (node, scalar) for row r = lane (0..31).
    int   mA;  float sA;
    {
        const int r = lane;
        if (r == 0 || r == 17) { mA = n1; sA = w1; }
        else if (r <= 16)      { mA = in_sample [n1 * SUP + (r - 1)];
                                 sA = in_amnt   [n1 * SUP + (r - 1)]; }
        else                   { mA = out_sample[n1 * SUP + (r - 18)];
                                 sA = out_amnt  [n1 * SUP + (r - 18)]; }
    }
    // Rows 32,33 (j = 14,15 of the out-branch) on lanes 0,1.
    int mB = 0; float sB = 0.f;
    if (lane < 2) {
        mB = out_sample[n1 * SUP + (14 + lane)];
        sB = out_amnt  [n1 * SUP + (14 + lane)];
    }

    // Weights into smem.
    {
        const float wv = (lane == 0 || lane == 17) ? (w1 * w1) : (sA * w1);
        wbuf[warp * GROUP_ROWS + lane] = wv;
        if (lane < 2) wbuf[warp * GROUP_ROWS + 32 + lane] = sB * w1;
    }

    // Fill phase: gather feature rows into smem in final output layout.
    // STS is stride-1 -> conflict-free; no alignment games needed.
    float* rowp = buf + warp * (GROUP_ROWS * ROW_LEN);
    #pragma unroll 4
    for (int rr = 0; rr < GROUP_ROWS; rr++, rowp += ROW_LEN) {
        int m; float s;
        if (rr < 32) {
            m = __shfl_sync(0xffffffffu, mA, rr);
            s = __shfl_sync(0xffffffffu, sA, rr);
        } else {
            m = __shfl_sync(0xffffffffu, mB, rr - 32);
            s = __shfl_sync(0xffffffffu, sB, rr - 32);
        }
        const float* src = features + (size_t)m * FDIM;
        const float v0 = __ldg(src + lane);        // feats 0..31  (1 wavefront)
        const float v1 = __ldg(src + lane + 32);   // feats 32..63 (1 wavefront)
        if (lane == 0) rowp[0] = s;
        rowp[1 + lane]  = v0;
        rowp[33 + lane] = v1;
    }
    __syncthreads();

    // Drain phase: one bulk async copy per region, full-line aligned writes.
    if (threadIdx.x == 0) {
        asm volatile("fence.proxy.async.shared::cta;" ::: "memory");
        const uint32_t sbuf  = smem_u32(buf);
        const uint32_t swbuf = smem_u32(wbuf);
        float* fdst = feat_out + (size_t)blockIdx.x * CHUNK_FLOATS;
        float* wdst = w_out    + (size_t)blockIdx.x * WCHUNK;
        asm volatile("cp.async.bulk.global.shared::cta.bulk_group [%0], [%1], %2;"
                     :: "l"(fdst), "r"(sbuf), "n"(CHUNK_FLOATS * 4) : "memory");
        asm volatile("cp.async.bulk.global.shared::cta.bulk_group [%0], [%1], %2;"
                     :: "l"(wdst), "r"(swbuf), "n"(WCHUNK * 4) : "memory");
        asm volatile("cp.async.bulk.commit_group;" ::: "memory");
        asm volatile("cp.async.bulk.wait_group 0;" ::: "memory");
    }
}

extern "C" void kernel_launch(void* const* d_in, const int* in_sizes, int n_in,
                              void* d_out, int out_size) {
    const int*   node_ids = (const int*)  d_in[0];
    const float* features = (const float*)d_in[1];
    const int*   in_samp  = (const int*)  d_in[2];
    const int*   out_samp = (const int*)  d_in[3];
    const float* in_amnt  = (const float*)d_in[4];
    const float* out_amnt = (const float*)d_in[5];

    float* feat_out = (float*)d_out;
    float* w_out    = feat_out + (size_t)BATCH_N * ROWS_PER_B * ROW_LEN;

    gae_gather_tma_kernel<<<N_BLOCKS, THREADS>>>(node_ids, features, in_samp, out_samp,
                                                 in_amnt, out_amnt, feat_out, w_out);
}

// round 9
// speedup vs baseline: 1.8951x; 1.8951x over previous
#include <cuda_runtime.h>
#include <cstdint>

// Problem constants: SUPPORT=(16,16), N_NODES=100000, F=64, B=4096
#define BATCH_N    4096
#define SUP        16
#define FDIM       64
#define ROW_LEN    65          // 1 weight col + 64 features
#define ROWS_PER_B 1088        // 2 * 16 * 34
#define GROUP_ROWS 34          // 2 + 2*16
#define N_GROUPS   (BATCH_N * 2 * SUP)   // 131072 warps
#define WARPS_PER_BLOCK 8
#define THREADS (WARPS_PER_BLOCK * 32)
#define FULLMASK 0xffffffffu

__global__ __launch_bounds__(THREADS)
void gae_gather_merge_kernel(const int*   __restrict__ node_ids,
                             const float* __restrict__ features,
                             const int*   __restrict__ in_sample,
                             const int*   __restrict__ out_sample,
                             const float* __restrict__ in_amnt,
                             const float* __restrict__ out_amnt,
                             float*       __restrict__ feat_out,
                             float*       __restrict__ w_out) {
    const int warp = threadIdx.x >> 5;
    const int lane = threadIdx.x & 31;
    const int g = blockIdx.x * WARPS_PER_BLOCK + warp;

    const int b    = g >> 5;        // 32 groups per batch element
    const int rem  = g & 31;
    const int half = rem >> 4;      // 0 = in-branch at hop1, 1 = out-branch
    const int i    = rem & 15;      // first-hop neighbor index

    const int n = node_ids[b];
    const int*   s1 = half ? out_sample : in_sample;
    const float* a1 = half ? out_amnt  : in_amnt;
    const int   n1 = s1[n * SUP + i];
    const float w1 = a1[n * SUP + i];

    // Per-lane (node, scalar) for row r = lane (0..31).
    int   mA;  float sA;
    {
        const int r = lane;
        if (r == 0 || r == 17) { mA = n1; sA = w1; }
        else if (r <= 16)      { mA = in_sample [n1 * SUP + (r - 1)];
                                 sA = in_amnt   [n1 * SUP + (r - 1)]; }
        else                   { mA = out_sample[n1 * SUP + (r - 18)];
                                 sA = out_amnt  [n1 * SUP + (r - 18)]; }
    }
    // Rows 32,33 on lanes 0,1.
    int mB = 0; float sB = 0.f;
    if (lane < 2) {
        mB = out_sample[n1 * SUP + (14 + lane)];
        sB = out_amnt  [n1 * SUP + (14 + lane)];
    }

    const uint32_t rowbase = (uint32_t)b * ROWS_PER_B + half * 544 + i * GROUP_ROWS;

    // Weights: w1^2 for self-rows, w2*w1 otherwise.
    {
        const float wv = (lane == 0 || lane == 17) ? (w1 * w1) : (sA * w1);
        __stcs(&w_out[rowbase + lane], wv);
        if (lane < 2) __stcs(&w_out[rowbase + 32 + lane], sB * w1);
    }

    // ---- Feature rows: rotated loads + merged full-line stores ----
    const uint32_t G = rowbase * ROW_LEN;      // flat float index of group start (<2^31)
    int a = (int)(G & 31);                     // row-start misalignment (advances +1/row)
    int k = (lane - a - 1) & 31;               // rotated lane for loads
    // Invariant at top of iteration rr: myp = basep_{rr-1} + lane (line-aligned base + lane)
    float* myp = feat_out + (G - (uint32_t)a) + (uint32_t)lane;

    // Row 0 (prologue): predicated head + full chunk1.
    int   m = __shfl_sync(FULLMASK, mA, 0);
    float s = __shfl_sync(FULLMASK, sA, 0);
    const float* src = features + (size_t)m * FDIM;
    float v0 = __ldg(src + k);                 // feats, rotated (1 wavefront)
    float v1 = __ldg(src + k + 32);
    if (lane >= a) __stcs(&myp[0], (lane == a) ? s : v0);   // head: lanes < a belong to prev group
    __stcs(&myp[32], (lane <= a) ? v0 : v1);                // chunk1, full line

    #pragma unroll 4
    for (int rr = 1; rr < GROUP_ROWS; rr++) {
        const float pv1 = v1;
        const int   pa  = a;
        a = (a + 1) & 31;
        k = (k - 1) & 31;
        m = __shfl_sync(FULLMASK, (rr < 32) ? mA : mB, rr & 31);
        s = __shfl_sync(FULLMASK, (rr < 32) ? sA : sB, rr & 31);
        src = features + (size_t)m * FDIM;
        v0 = __ldg(src + k);
        v1 = __ldg(src + k + 32);

        // Merged line: prev row's tail (lanes <= pa, pv1) + cur row's head
        // (lane == a -> scalar, lane > a -> v0). When a==0 it degenerates to
        // the full prev-tail line (all lanes <= pa=31).
        const float mv = (lane <= pa) ? pv1 : ((lane == a) ? s : v0);
        __stcs(&myp[64], mv);

        if (a == 0) {   // wrap: cur row is line-aligned; emit its full head + chunk1
            __stcs(&myp[96],  (lane == 0) ? s : v0);
            __stcs(&myp[128], (lane == 0) ? v0 : v1);   // chunk1 with a==0
            myp += 96;
        } else {
            __stcs(&myp[96],  (lane <= a) ? v0 : v1);   // chunk1, full line
            myp += 64;
        }
    }
    // Tail: row 33's last partial line (lanes <= a_33); lanes above belong to next group.
    if (lane <= a) __stcs(&myp[64], v1);
}

extern "C" void kernel_launch(void* const* d_in, const int* in_sizes, int n_in,
                              void* d_out, int out_size) {
    const int*   node_ids = (const int*)  d_in[0];
    const float* features = (const float*)d_in[1];
    const int*   in_samp  = (const int*)  d_in[2];
    const int*   out_samp = (const int*)  d_in[3];
    const float* in_amnt  = (const float*)d_in[4];
    const float* out_amnt = (const float*)d_in[5];

    float* feat_out = (float*)d_out;
    float* w_out    = feat_out + (size_t)BATCH_N * ROWS_PER_B * ROW_LEN;

    const int blocks = N_GROUPS / WARPS_PER_BLOCK;   // 16384
    gae_gather_merge_kernel<<<blocks, THREADS>>>(node_ids, features, in_samp, out_samp,
                                                 in_amnt, out_amnt, feat_out, w_out);
}